// round 8
// baseline (speedup 1.0000x reference)
#include <cuda_runtime.h>
#include <cstdint>

// WaveNet dilated causal conv stack.
// 2-CTA cluster per batch element; fused conv+io; ping-pong h in SMEM.
// 4 positions per thread (float4) for layers >=2, float2 pairs for layers 0-1.
// Scalar constant weights (uniform LDCU path). Producer-push halo exchange.
// Split points: M0 = M1 = 1088; M_i = 1084 + 2^(i+1) for i >= 1.

#define NTH 288
#define LBUF 2176
#define FRAME 128
#define TFULL 4096

typedef unsigned long long u64;

#define OC0   0
#define OCK   24      // [(i-1)*3+w][ci][co]
#define OCB   1752    // [i][co]
#define OIOK  1832    // [i][ci][co]
#define OIOB  2408    // [i][co]
#define OMIX  2480    // [i][co]
#define OMIXB 2560
#define NW    2561

__constant__ float Wc[NW];
__device__ float Wstage[NW];

__device__ __forceinline__ uint32_t s2u(const void* p) {
    return (uint32_t)__cvta_generic_to_shared(p);
}
__device__ __forceinline__ uint32_t mapa_peer(uint32_t a, uint32_t peer) {
    uint32_t r;
    asm volatile("mapa.shared::cluster.u32 %0, %1, %2;" : "=r"(r) : "r"(a), "r"(peer));
    return r;
}
__device__ __forceinline__ void st_dsm64(uint32_t a, float x, float y) {
    u64 v = (u64)__float_as_uint(x) | ((u64)__float_as_uint(y) << 32);
    asm volatile("st.shared::cluster.b64 [%0], %1;" :: "r"(a), "l"(v) : "memory");
}
__device__ __forceinline__ void st_dsm128(uint32_t a, float x, float y, float z, float w) {
    asm volatile("st.shared::cluster.v4.b32 [%0], {%1,%2,%3,%4};"
                 :: "r"(a), "r"(__float_as_uint(x)), "r"(__float_as_uint(y)),
                    "r"(__float_as_uint(z)), "r"(__float_as_uint(w)) : "memory");
}
#define CS() do { asm volatile("barrier.cluster.arrive.aligned;" ::: "memory"); \
                  asm volatile("barrier.cluster.wait.aligned;" ::: "memory"); } while(0)

__global__ void pack_weights(const float* __restrict__ c0,  const float* __restrict__ ck,
                             const float* __restrict__ cb,  const float* __restrict__ iok,
                             const float* __restrict__ iob, const float* __restrict__ mix,
                             const float* __restrict__ mixb) {
    int i = blockIdx.x * blockDim.x + threadIdx.x;
    if (i >= NW) return;
    float v;
    if      (i < OCK)   v = c0[i - OC0];
    else if (i < OCB)   v = ck[i - OCK];
    else if (i < OIOK)  v = cb[i - OCB];
    else if (i < OIOB)  v = iok[i - OIOK];
    else if (i < OMIX)  v = iob[i - OIOB];
    else if (i < OMIXB) v = mix[i - OMIX];
    else                v = mixb[0];
    Wstage[i] = v;
}

extern __shared__ float smem[];

__global__ __launch_bounds__(NTH) __cluster_dims__(2, 1, 1)
void wavenet_kernel(const float* __restrict__ X, float* __restrict__ out)
{
    float* xb   = smem;              // LBUF
    float* hA   = smem + LBUF;       // 8*LBUF   h[c*LBUF + l]
    float* hB   = smem + 9 * LBUF;   // 8*LBUF
    float* oacc = smem + 17 * LBUF;  // FRAME

    const int tid = threadIdx.x;
    uint32_t rank;
    asm("mov.u32 %0, %%cluster_ctarank;" : "=r"(rank));
    const uint32_t peer = rank ^ 1u;
    const int b = blockIdx.x >> 1;
    const float* x = X + b * TFULL + (TFULL - LBUF);

    for (int l = tid; l < LBUF; l += NTH) xb[l] = x[l];
    if (rank && tid < FRAME) oacc[tid] = Wc[OMIXB];
    __syncthreads();

    // ---- layer 0 (pairs) -> hA; rank0 pushes [M-4, M) (layer-1 halo, d=2 -> width 4) ----
    {
        const int M = 1088;
        const int lo = rank ? M : 2;
        const int hi = rank ? LBUF : M;
        const uint32_t pbase = mapa_peer(s2u(hA), peer);
        for (int l = lo + 2 * tid; l < hi; l += 2 * NTH) {
            float2 A = *(const float2*)&xb[l - 2];
            float2 B = *(const float2*)&xb[l];
            float acc0[8], acc1[8];
#pragma unroll
            for (int co = 0; co < 8; co++) {
                float w0 = Wc[OC0 + co], w1 = Wc[OC0 + 8 + co], w2 = Wc[OC0 + 16 + co];
                float bb = Wc[OCB + co];
                acc0[co] = fmaxf(fmaf(B.x, w2, fmaf(A.y, w1, fmaf(A.x, w0, bb))), 0.0f);
                acc1[co] = fmaxf(fmaf(B.y, w2, fmaf(B.x, w1, fmaf(A.y, w0, bb))), 0.0f);
            }
            if (l >= LBUF - FRAME) {
                float m0 = 0.0f, m1 = 0.0f;
#pragma unroll
                for (int co = 0; co < 8; co++) {
                    float mw = Wc[OMIX + co];
                    m0 = fmaf(acc0[co], mw, m0); m1 = fmaf(acc1[co], mw, m1);
                }
                oacc[l - (LBUF - FRAME)]     += m0;
                oacc[l - (LBUF - FRAME) + 1] += m1;
            }
            const bool push = rank ? false : (l >= M - 4 && l < M);
#pragma unroll
            for (int co = 0; co < 8; co++) {
                float bb = Wc[OIOB + co];
                float a0 = bb + B.x, a1 = bb + B.y;
#pragma unroll
                for (int ci = 0; ci < 8; ci++) {
                    float wk = Wc[OIOK + ci * 8 + co];
                    a0 = fmaf(acc0[ci], wk, a0); a1 = fmaf(acc1[ci], wk, a1);
                }
                const int idx = co * LBUF + l;
                *(float2*)(hA + idx) = make_float2(a0, a1);
                if (push) st_dsm64(pbase + (uint32_t)idx * 4u, a0, a1);
            }
        }
    }
    CS();

    // ---- layer 1 (pairs, d=2) hA -> hB; pushes [1084,1088) / [1088,1092) ----
    {
        const int i = 1, d = 2, M = 1088, dn = 4;
        const int lo = rank ? M : 6;
        const int hi = rank ? LBUF : M;
        const uint32_t pbase = mapa_peer(s2u(hB), peer);
        for (int l = lo + 2 * tid; l < hi; l += 2 * NTH) {
            float acc0[8], acc1[8], hl0[8], hl1[8];
#pragma unroll
            for (int co = 0; co < 8; co++) { acc0[co] = Wc[OCB + i * 8 + co]; acc1[co] = acc0[co]; }
#pragma unroll
            for (int w = 0; w < 3; w++) {
                const int off = (2 - w) * d;
#pragma unroll
                for (int ci = 0; ci < 8; ci++) {
                    float2 v = *(const float2*)(hA + ci * LBUF + (l - off));
                    if (w == 2) { hl0[ci] = v.x; hl1[ci] = v.y; }
#pragma unroll
                    for (int co = 0; co < 8; co++) {
                        float wk = Wc[OCK + (((i - 1) * 3 + w) * 8 + ci) * 8 + co];
                        acc0[co] = fmaf(v.x, wk, acc0[co]); acc1[co] = fmaf(v.y, wk, acc1[co]);
                    }
                }
            }
#pragma unroll
            for (int co = 0; co < 8; co++) { acc0[co] = fmaxf(acc0[co], 0.0f); acc1[co] = fmaxf(acc1[co], 0.0f); }
            if (l >= LBUF - FRAME) {
                float m0 = 0.0f, m1 = 0.0f;
#pragma unroll
                for (int co = 0; co < 8; co++) {
                    float mw = Wc[OMIX + i * 8 + co];
                    m0 = fmaf(acc0[co], mw, m0); m1 = fmaf(acc1[co], mw, m1);
                }
                oacc[l - (LBUF - FRAME)]     += m0;
                oacc[l - (LBUF - FRAME) + 1] += m1;
            }
            const bool push = rank ? (l >= M && l < M + dn) : (l >= M - dn && l < M);
#pragma unroll
            for (int co = 0; co < 8; co++) {
                float bb = Wc[OIOB + i * 8 + co];
                float a0 = bb + hl0[co], a1 = bb + hl1[co];
#pragma unroll
                for (int ci = 0; ci < 8; ci++) {
                    float wk = Wc[OIOK + (i * 8 + ci) * 8 + co];
                    a0 = fmaf(acc0[ci], wk, a0); a1 = fmaf(acc1[ci], wk, a1);
                }
                const int idx = co * LBUF + l;
                *(float2*)(hB + idx) = make_float2(a0, a1);
                if (push) st_dsm64(pbase + (uint32_t)idx * 4u, a0, a1);
            }
        }
    }
    CS();

    // ---- layers 2..8 (quads): one float4 group per thread ----
#pragma unroll
    for (int i = 2; i < 9; i++) {
        const int d  = 1 << i;
        const int S  = (4 << i) - 2;           // 2*(2^{i+1}-1)
        const int M  = 1084 + (2 << i);        // multiple of 4
        const int dn = 2 << i;
        float* cur = (i & 1) ? hA : hB;
        float* nxt = (i & 1) ? hB : hA;
        const uint32_t pbase = mapa_peer(s2u(nxt), peer);

        const int lo = rank ? M : (S - 2);     // S-2 mult of 4; 2 garbage pos never read downstream
        const int hi = rank ? LBUF : M;
        const int l = lo + 4 * tid;
        if (l < hi) {
            float a0[8], a1[8], a2[8], a3[8];
            float4 hl[8];
#pragma unroll
            for (int co = 0; co < 8; co++) {
                float cb = Wc[OCB + i * 8 + co];
                a0[co] = cb; a1[co] = cb; a2[co] = cb; a3[co] = cb;
            }
#pragma unroll
            for (int w = 0; w < 3; w++) {
                const int off = (2 - w) * d;
#pragma unroll
                for (int ci = 0; ci < 8; ci++) {
                    float4 v = *(const float4*)(cur + ci * LBUF + (l - off));
                    if (w == 2) hl[ci] = v;
#pragma unroll
                    for (int co = 0; co < 8; co++) {
                        float wk = Wc[OCK + (((i - 1) * 3 + w) * 8 + ci) * 8 + co];
                        a0[co] = fmaf(v.x, wk, a0[co]); a1[co] = fmaf(v.y, wk, a1[co]);
                        a2[co] = fmaf(v.z, wk, a2[co]); a3[co] = fmaf(v.w, wk, a3[co]);
                    }
                }
            }
#pragma unroll
            for (int co = 0; co < 8; co++) {
                a0[co] = fmaxf(a0[co], 0.0f); a1[co] = fmaxf(a1[co], 0.0f);
                a2[co] = fmaxf(a2[co], 0.0f); a3[co] = fmaxf(a3[co], 0.0f);
            }
            if (l >= LBUF - FRAME) {
                float m0 = 0, m1 = 0, m2 = 0, m3 = 0;
#pragma unroll
                for (int co = 0; co < 8; co++) {
                    float mw = Wc[OMIX + i * 8 + co];
                    m0 = fmaf(a0[co], mw, m0); m1 = fmaf(a1[co], mw, m1);
                    m2 = fmaf(a2[co], mw, m2); m3 = fmaf(a3[co], mw, m3);
                }
                float4* op = (float4*)&oacc[l - (LBUF - FRAME)];
                float4 o = *op;
                o.x += m0; o.y += m1; o.z += m2; o.w += m3;
                *op = o;
            }
            bool push;
            if (i == 8)
                push = rank ? false : ((l >= 1024 && l < 1152) || (l >= 1536 && l < 1596));
            else
                push = rank ? (l >= M && l < M + dn) : (l >= M - dn && l < M);
#pragma unroll
            for (int co = 0; co < 8; co++) {
                float bb = Wc[OIOB + i * 8 + co];
                float b0 = bb + hl[co].x, b1 = bb + hl[co].y, b2 = bb + hl[co].z, b3 = bb + hl[co].w;
#pragma unroll
                for (int ci = 0; ci < 8; ci++) {
                    float wk = Wc[OIOK + (i * 8 + ci) * 8 + co];
                    b0 = fmaf(a0[ci], wk, b0); b1 = fmaf(a1[ci], wk, b1);
                    b2 = fmaf(a2[ci], wk, b2); b3 = fmaf(a3[ci], wk, b3);
                }
                const int idx = co * LBUF + l;
                *(float4*)(nxt + idx) = make_float4(b0, b1, b2, b3);
                if (push) st_dsm128(pbase + (uint32_t)idx * 4u, b0, b1, b2, b3);
            }
        }
        CS();
    }

    // ---- layer 9 (rank1 only, quads over last FRAME): reads own hA ----
    if (rank) {
        const int i = 9, d = 512;
        const int l = (LBUF - FRAME) + 4 * tid;
        if (l < LBUF) {
            float a0[8], a1[8], a2[8], a3[8];
#pragma unroll
            for (int co = 0; co < 8; co++) {
                float cb = Wc[OCB + i * 8 + co];
                a0[co] = cb; a1[co] = cb; a2[co] = cb; a3[co] = cb;
            }
#pragma unroll
            for (int w = 0; w < 3; w++) {
                const int off = (2 - w) * d;
#pragma unroll
                for (int ci = 0; ci < 8; ci++) {
                    float4 v = *(const float4*)(hA + ci * LBUF + (l - off));
#pragma unroll
                    for (int co = 0; co < 8; co++) {
                        float wk = Wc[OCK + (((i - 1) * 3 + w) * 8 + ci) * 8 + co];
                        a0[co] = fmaf(v.x, wk, a0[co]); a1[co] = fmaf(v.y, wk, a1[co]);
                        a2[co] = fmaf(v.z, wk, a2[co]); a3[co] = fmaf(v.w, wk, a3[co]);
                    }
                }
            }
            float m0 = 0, m1 = 0, m2 = 0, m3 = 0;
#pragma unroll
            for (int co = 0; co < 8; co++) {
                float mw = Wc[OMIX + i * 8 + co];
                m0 = fmaf(fmaxf(a0[co], 0.0f), mw, m0);
                m1 = fmaf(fmaxf(a1[co], 0.0f), mw, m1);
                m2 = fmaf(fmaxf(a2[co], 0.0f), mw, m2);
                m3 = fmaf(fmaxf(a3[co], 0.0f), mw, m3);
            }
            float4* op = (float4*)&oacc[l - (LBUF - FRAME)];
            float4 o = *op;
            o.x += m0; o.y += m1; o.z += m2; o.w += m3;
            *op = o;
        }
        __syncthreads();
        if (tid < FRAME) out[b * FRAME + tid] = oacc[tid];
    }
}

static const int SMEM_BYTES = (17 * LBUF + FRAME) * (int)sizeof(float);

extern "C" void kernel_launch(void* const* d_in, const int* in_sizes, int n_in,
                              void* d_out, int out_size) {
    (void)in_sizes; (void)n_in; (void)out_size;
    cudaFuncSetAttribute(wavenet_kernel, cudaFuncAttributeMaxDynamicSharedMemorySize, SMEM_BYTES);

    pack_weights<<<(NW + 511) / 512, 512>>>(
        (const float*)d_in[1], (const float*)d_in[2], (const float*)d_in[3],
        (const float*)d_in[4], (const float*)d_in[5], (const float*)d_in[6],
        (const float*)d_in[7]);

    void* wp = nullptr;
    cudaGetSymbolAddress(&wp, Wstage);
    cudaMemcpyToSymbolAsync(Wc, wp, NW * sizeof(float), 0, cudaMemcpyDeviceToDevice, 0);

    wavenet_kernel<<<128, NTH, SMEM_BYTES>>>((const float*)d_in[0], (float*)d_out);
}

// round 10
// speedup vs baseline: 1.1595x; 1.1595x over previous
#include <cuda_runtime.h>
#include <cstdint>

// WaveNet dilated causal conv stack.
// 2-CTA cluster per batch element; fused conv+io; ping-pong h in SMEM.
// Scalar positions, NTH=512, strided loop (~2 iters/thread/layer).
// Scalar constant weights (uniform path). Producer-push halo exchange.
// Split points: M_i = 1086 + 2^(i+1)  (verified geometry from R6).
// Identical to R9 source — R9 bench was an infra failure, not a kernel result.

#define NTH 512
#define LBUF 2176
#define FRAME 128
#define TFULL 4096

#define OC0   0
#define OCK   24      // [(i-1)*3+w][ci][co]
#define OCB   1752    // [i][co]
#define OIOK  1832    // [i][ci][co]
#define OIOB  2408    // [i][co]
#define OMIX  2480    // [i][co]
#define OMIXB 2560
#define NW    2561

__constant__ float Wc[NW];
__device__ float Wstage[NW];

__device__ __forceinline__ uint32_t s2u(const void* p) {
    return (uint32_t)__cvta_generic_to_shared(p);
}
__device__ __forceinline__ uint32_t mapa_peer(uint32_t a, uint32_t peer) {
    uint32_t r;
    asm volatile("mapa.shared::cluster.u32 %0, %1, %2;" : "=r"(r) : "r"(a), "r"(peer));
    return r;
}
__device__ __forceinline__ void st_dsm32(uint32_t a, float x) {
    asm volatile("st.shared::cluster.b32 [%0], %1;" :: "r"(a), "r"(__float_as_uint(x)) : "memory");
}
#define CS() do { asm volatile("barrier.cluster.arrive.aligned;" ::: "memory"); \
                  asm volatile("barrier.cluster.wait.aligned;" ::: "memory"); } while(0)

__global__ void pack_weights(const float* __restrict__ c0,  const float* __restrict__ ck,
                             const float* __restrict__ cb,  const float* __restrict__ iok,
                             const float* __restrict__ iob, const float* __restrict__ mix,
                             const float* __restrict__ mixb) {
    int i = blockIdx.x * blockDim.x + threadIdx.x;
    if (i >= NW) return;
    float v;
    if      (i < OCK)   v = c0[i - OC0];
    else if (i < OCB)   v = ck[i - OCK];
    else if (i < OIOK)  v = cb[i - OCB];
    else if (i < OIOB)  v = iok[i - OIOK];
    else if (i < OMIX)  v = iob[i - OIOB];
    else if (i < OMIXB) v = mix[i - OMIX];
    else                v = mixb[0];
    Wstage[i] = v;
}

extern __shared__ float smem[];

__global__ __launch_bounds__(NTH) __cluster_dims__(2, 1, 1)
void wavenet_kernel(const float* __restrict__ X, float* __restrict__ out)
{
    float* xb   = smem;              // LBUF
    float* hA   = smem + LBUF;       // 8*LBUF   h[c*LBUF + l]
    float* hB   = smem + 9 * LBUF;   // 8*LBUF
    float* oacc = smem + 17 * LBUF;  // FRAME

    const int tid = threadIdx.x;
    uint32_t rank;
    asm("mov.u32 %0, %%cluster_ctarank;" : "=r"(rank));
    const uint32_t peer = rank ^ 1u;
    const int b = blockIdx.x >> 1;
    const float* x = X + b * TFULL + (TFULL - LBUF);

    for (int l = tid; l < LBUF; l += NTH) xb[l] = x[l];
    if (rank && tid < FRAME) oacc[tid] = Wc[OMIXB];
    __syncthreads();

    // ---- layer 0 -> hA; push windows width 2 around M0=1088 ----
    {
        const int M = 1088, dn = 2;
        const int lo = rank ? M : 2;
        const int hi = rank ? LBUF : M;
        const uint32_t pbase = mapa_peer(s2u(hA), peer);
        for (int l = lo + tid; l < hi; l += NTH) {
            float x0 = xb[l - 2], x1 = xb[l - 1], x2 = xb[l];
            float acc[8];
#pragma unroll
            for (int co = 0; co < 8; co++) {
                float a = Wc[OCB + co];
                a = fmaf(x0, Wc[OC0 + co], a);
                a = fmaf(x1, Wc[OC0 + 8 + co], a);
                a = fmaf(x2, Wc[OC0 + 16 + co], a);
                acc[co] = fmaxf(a, 0.0f);
            }
            if (l >= LBUF - FRAME) {
                float m = 0.0f;
#pragma unroll
                for (int co = 0; co < 8; co++) m = fmaf(acc[co], Wc[OMIX + co], m);
                oacc[l - (LBUF - FRAME)] += m;
            }
            const bool push = rank ? (l >= M && l < M + dn) : (l >= M - dn && l < M);
#pragma unroll
            for (int co = 0; co < 8; co++) {
                float a = Wc[OIOB + co] + x2;
#pragma unroll
                for (int ci = 0; ci < 8; ci++) a = fmaf(acc[ci], Wc[OIOK + ci * 8 + co], a);
                const int idx = co * LBUF + l;
                hA[idx] = a;
                if (push) st_dsm32(pbase + (uint32_t)idx * 4u, a);
            }
        }
    }
    CS();

    // ---- layers 1..8 (fused), ping-pong, push halos ----
#pragma unroll
    for (int i = 1; i < 9; i++) {
        const int d  = 1 << i;
        const int S  = (4 << i) - 2;           // 2*(2^{i+1}-1)
        const int M  = 1086 + (2 << i);        // split point
        const int dn = 2 << i;                 // halo width for layer i+1
        float* cur = (i & 1) ? hA : hB;
        float* nxt = (i & 1) ? hB : hA;
        const uint32_t pbase = mapa_peer(s2u(nxt), peer);

        const int lo = rank ? M : S;
        const int hi = rank ? LBUF : M;
        for (int l = lo + tid; l < hi; l += NTH) {
            float acc[8], hl[8];
#pragma unroll
            for (int co = 0; co < 8; co++) acc[co] = Wc[OCB + i * 8 + co];
#pragma unroll
            for (int w = 0; w < 3; w++) {
                const int off = (2 - w) * d;
#pragma unroll
                for (int ci = 0; ci < 8; ci++) {
                    float v = cur[ci * LBUF + l - off];
                    if (w == 2) hl[ci] = v;
#pragma unroll
                    for (int co = 0; co < 8; co++)
                        acc[co] = fmaf(v, Wc[OCK + (((i - 1) * 3 + w) * 8 + ci) * 8 + co], acc[co]);
                }
            }
#pragma unroll
            for (int co = 0; co < 8; co++) acc[co] = fmaxf(acc[co], 0.0f);
            if (l >= LBUF - FRAME) {
                float m = 0.0f;
#pragma unroll
                for (int co = 0; co < 8; co++) m = fmaf(acc[co], Wc[OMIX + i * 8 + co], m);
                oacc[l - (LBUF - FRAME)] += m;
            }
            bool push;
            if (i == 8)   // layer 9 runs only on rank1; rank0 pushes the strips it owns
                push = rank ? false : ((l >= 1024 && l < 1152) || (l >= 1536 && l < 1598));
            else
                push = rank ? (l >= M && l < M + dn) : (l >= M - dn && l < M);
#pragma unroll
            for (int co = 0; co < 8; co++) {
                float a = Wc[OIOB + i * 8 + co] + hl[co];
#pragma unroll
                for (int ci = 0; ci < 8; ci++)
                    a = fmaf(acc[ci], Wc[OIOK + (i * 8 + ci) * 8 + co], a);
                const int idx = co * LBUF + l;
                nxt[idx] = a;
                if (push) st_dsm32(pbase + (uint32_t)idx * 4u, a);
            }
        }
        CS();
    }

    // ---- layer 9 (rank1 only): reads own hA, last FRAME positions ----
    if (rank) {
        const int i = 9, d = 512;
        for (int l = (LBUF - FRAME) + tid; l < LBUF; l += NTH) {
            float acc[8];
#pragma unroll
            for (int co = 0; co < 8; co++) acc[co] = Wc[OCB + i * 8 + co];
#pragma unroll
            for (int w = 0; w < 3; w++) {
                const int off = (2 - w) * d;
#pragma unroll
                for (int ci = 0; ci < 8; ci++) {
                    float v = hA[ci * LBUF + l - off];
#pragma unroll
                    for (int co = 0; co < 8; co++)
                        acc[co] = fmaf(v, Wc[OCK + (((i - 1) * 3 + w) * 8 + ci) * 8 + co], acc[co]);
                }
            }
            float m = 0.0f;
#pragma unroll
            for (int co = 0; co < 8; co++)
                m = fmaf(fmaxf(acc[co], 0.0f), Wc[OMIX + i * 8 + co], m);
            oacc[l - (LBUF - FRAME)] += m;
        }
        __syncthreads();
        if (tid < FRAME) out[b * FRAME + tid] = oacc[tid];
    }
}

static const int SMEM_BYTES = (17 * LBUF + FRAME) * (int)sizeof(float);

extern "C" void kernel_launch(void* const* d_in, const int* in_sizes, int n_in,
                              void* d_out, int out_size) {
    (void)in_sizes; (void)n_in; (void)out_size;
    cudaFuncSetAttribute(wavenet_kernel, cudaFuncAttributeMaxDynamicSharedMemorySize, SMEM_BYTES);

    pack_weights<<<(NW + 511) / 512, 512>>>(
        (const float*)d_in[1], (const float*)d_in[2], (const float*)d_in[3],
        (const float*)d_in[4], (const float*)d_in[5], (const float*)d_in[6],
        (const float*)d_in[7]);

    void* wp = nullptr;
    cudaGetSymbolAddress(&wp, Wstage);
    cudaMemcpyToSymbolAsync(Wc, wp, NW * sizeof(float), 0, cudaMemcpyDeviceToDevice, 0);

    wavenet_kernel<<<128, NTH, SMEM_BYTES>>>((const float*)d_in[0], (float*)d_out);
}

// round 11
// speedup vs baseline: 1.3252x; 1.1429x over previous
#include <cuda_runtime.h>
#include <cstdint>

// WaveNet dilated causal conv stack.
// 2-CTA cluster per batch element; fused conv+io; ping-pong h in SMEM.
// 2 positions per thread (float2), NTH=544 (one-shot bodies, 16 FMA chains).
// Scalar constant weights (uniform path). Producer-push halo exchange.
// Split points: M0=1088; M_i = 1086 + 2^(i+1) (geometry verified in R6/R10).

#define NTH 544
#define LBUF 2176
#define FRAME 128
#define TFULL 4096

typedef unsigned long long u64;

#define OC0   0
#define OCK   24      // [(i-1)*3+w][ci][co]
#define OCB   1752    // [i][co]
#define OIOK  1832    // [i][ci][co]
#define OIOB  2408    // [i][co]
#define OMIX  2480    // [i][co]
#define OMIXB 2560
#define NW    2561

__constant__ float Wc[NW];
__device__ float Wstage[NW];

__device__ __forceinline__ uint32_t s2u(const void* p) {
    return (uint32_t)__cvta_generic_to_shared(p);
}
__device__ __forceinline__ uint32_t mapa_peer(uint32_t a, uint32_t peer) {
    uint32_t r;
    asm volatile("mapa.shared::cluster.u32 %0, %1, %2;" : "=r"(r) : "r"(a), "r"(peer));
    return r;
}
__device__ __forceinline__ void st_dsm64(uint32_t a, float x, float y) {
    u64 v = (u64)__float_as_uint(x) | ((u64)__float_as_uint(y) << 32);
    asm volatile("st.shared::cluster.b64 [%0], %1;" :: "r"(a), "l"(v) : "memory");
}
#define CS() do { asm volatile("barrier.cluster.arrive.aligned;" ::: "memory"); \
                  asm volatile("barrier.cluster.wait.aligned;" ::: "memory"); } while(0)

__global__ void pack_weights(const float* __restrict__ c0,  const float* __restrict__ ck,
                             const float* __restrict__ cb,  const float* __restrict__ iok,
                             const float* __restrict__ iob, const float* __restrict__ mix,
                             const float* __restrict__ mixb) {
    int i = blockIdx.x * blockDim.x + threadIdx.x;
    if (i >= NW) return;
    float v;
    if      (i < OCK)   v = c0[i - OC0];
    else if (i < OCB)   v = ck[i - OCK];
    else if (i < OIOK)  v = cb[i - OCB];
    else if (i < OIOB)  v = iok[i - OIOB + 0 - (OIOB - OIOK) + (i - OIOK) - (i - OIOK)]; // identity below
    else if (i < OMIX)  v = iob[i - OIOB];
    else if (i < OMIXB) v = mix[i - OMIX];
    else                v = mixb[0];
    if (i >= OIOK && i < OIOB) v = iok[i - OIOK];
    Wstage[i] = v;
}

extern __shared__ float smem[];

__global__ __launch_bounds__(NTH) __cluster_dims__(2, 1, 1)
void wavenet_kernel(const float* __restrict__ X, float* __restrict__ out)
{
    float* xb   = smem;              // LBUF
    float* hA   = smem + LBUF;       // 8*LBUF   h[c*LBUF + l]
    float* hB   = smem + 9 * LBUF;   // 8*LBUF
    float* oacc = smem + 17 * LBUF;  // FRAME

    const int tid = threadIdx.x;
    uint32_t rank;
    asm("mov.u32 %0, %%cluster_ctarank;" : "=r"(rank));
    const uint32_t peer = rank ^ 1u;
    const int b = blockIdx.x >> 1;
    const float* x = X + b * TFULL + (TFULL - LBUF);

    for (int l = tid; l < LBUF; l += NTH) xb[l] = x[l];
    if (rank && tid < FRAME) oacc[tid] = Wc[OMIXB];
    __syncthreads();

    // ---- layer 0 (pairs) -> hA; push windows [1086,1088) / [1088,1090) ----
    {
        const int M = 1088, dn = 2;
        const int lo = rank ? M : 2;
        const int hi = rank ? LBUF : M;
        const uint32_t pbase = mapa_peer(s2u(hA), peer);
        for (int l = lo + 2 * tid; l < hi; l += 2 * NTH) {
            float2 A = *(const float2*)&xb[l - 2];
            float2 B = *(const float2*)&xb[l];
            float acc0[8], acc1[8];
#pragma unroll
            for (int co = 0; co < 8; co++) {
                float w0 = Wc[OC0 + co], w1 = Wc[OC0 + 8 + co], w2 = Wc[OC0 + 16 + co];
                float bb = Wc[OCB + co];
                acc0[co] = fmaxf(fmaf(B.x, w2, fmaf(A.y, w1, fmaf(A.x, w0, bb))), 0.0f);
                acc1[co] = fmaxf(fmaf(B.y, w2, fmaf(B.x, w1, fmaf(A.y, w0, bb))), 0.0f);
            }
            if (l >= LBUF - FRAME) {
                float m0 = 0.0f, m1 = 0.0f;
#pragma unroll
                for (int co = 0; co < 8; co++) {
                    float mw = Wc[OMIX + co];
                    m0 = fmaf(acc0[co], mw, m0); m1 = fmaf(acc1[co], mw, m1);
                }
                oacc[l - (LBUF - FRAME)]     += m0;
                oacc[l - (LBUF - FRAME) + 1] += m1;
            }
            const bool push = rank ? (l >= M && l < M + dn) : (l >= M - dn && l < M);
#pragma unroll
            for (int co = 0; co < 8; co++) {
                float bb = Wc[OIOB + co];
                float a0 = bb + B.x, a1 = bb + B.y;
#pragma unroll
                for (int ci = 0; ci < 8; ci++) {
                    float wk = Wc[OIOK + ci * 8 + co];
                    a0 = fmaf(acc0[ci], wk, a0); a1 = fmaf(acc1[ci], wk, a1);
                }
                const int idx = co * LBUF + l;
                *(float2*)(hA + idx) = make_float2(a0, a1);
                if (push) st_dsm64(pbase + (uint32_t)idx * 4u, a0, a1);
            }
        }
    }
    CS();

    // ---- layers 1..8 (pairs), ping-pong, push halos ----
#pragma unroll
    for (int i = 1; i < 9; i++) {
        const int d  = 1 << i;
        const int S  = (4 << i) - 2;           // 2*(2^{i+1}-1)
        const int M  = 1086 + (2 << i);
        const int dn = 2 << i;                 // halo width for layer i+1
        float* cur = (i & 1) ? hA : hB;
        float* nxt = (i & 1) ? hB : hA;
        const uint32_t pbase = mapa_peer(s2u(nxt), peer);

        const int lo = rank ? M : S;
        const int hi = rank ? LBUF : M;
        for (int l = lo + 2 * tid; l < hi; l += 2 * NTH) {
            float acc0[8], acc1[8], hl0[8], hl1[8];
#pragma unroll
            for (int co = 0; co < 8; co++) { acc0[co] = Wc[OCB + i * 8 + co]; acc1[co] = acc0[co]; }
#pragma unroll
            for (int w = 0; w < 3; w++) {
                const int off = (2 - w) * d;
#pragma unroll
                for (int ci = 0; ci < 8; ci++) {
                    float2 v = *(const float2*)(cur + ci * LBUF + (l - off));
                    if (w == 2) { hl0[ci] = v.x; hl1[ci] = v.y; }
#pragma unroll
                    for (int co = 0; co < 8; co++) {
                        float wk = Wc[OCK + (((i - 1) * 3 + w) * 8 + ci) * 8 + co];
                        acc0[co] = fmaf(v.x, wk, acc0[co]); acc1[co] = fmaf(v.y, wk, acc1[co]);
                    }
                }
            }
#pragma unroll
            for (int co = 0; co < 8; co++) { acc0[co] = fmaxf(acc0[co], 0.0f); acc1[co] = fmaxf(acc1[co], 0.0f); }
            if (l >= LBUF - FRAME) {
                float m0 = 0.0f, m1 = 0.0f;
#pragma unroll
                for (int co = 0; co < 8; co++) {
                    float mw = Wc[OMIX + i * 8 + co];
                    m0 = fmaf(acc0[co], mw, m0); m1 = fmaf(acc1[co], mw, m1);
                }
                oacc[l - (LBUF - FRAME)]     += m0;
                oacc[l - (LBUF - FRAME) + 1] += m1;
            }
            bool push;
            if (i == 8)   // layer 9 runs on rank1 only; rank0 pushes its strips
                push = rank ? false : ((l >= 1024 && l < 1152) || (l >= 1536 && l < 1598));
            else
                push = rank ? (l >= M && l < M + dn) : (l >= M - dn && l < M);
#pragma unroll
            for (int co = 0; co < 8; co++) {
                float bb = Wc[OIOB + i * 8 + co];
                float a0 = bb + hl0[co], a1 = bb + hl1[co];
#pragma unroll
                for (int ci = 0; ci < 8; ci++) {
                    float wk = Wc[OIOK + (i * 8 + ci) * 8 + co];
                    a0 = fmaf(acc0[ci], wk, a0); a1 = fmaf(acc1[ci], wk, a1);
                }
                const int idx = co * LBUF + l;
                *(float2*)(nxt + idx) = make_float2(a0, a1);
                if (push) st_dsm64(pbase + (uint32_t)idx * 4u, a0, a1);
            }
        }
        CS();
    }

    // ---- layer 9 (rank1 only, pairs): reads own hA, last FRAME positions ----
    if (rank) {
        const int i = 9, d = 512;
        for (int l = (LBUF - FRAME) + 2 * tid; l < LBUF; l += 2 * NTH) {
            float acc0[8], acc1[8];
#pragma unroll
            for (int co = 0; co < 8; co++) { acc0[co] = Wc[OCB + i * 8 + co]; acc1[co] = acc0[co]; }
#pragma unroll
            for (int w = 0; w < 3; w++) {
                const int off = (2 - w) * d;
#pragma unroll
                for (int ci = 0; ci < 8; ci++) {
                    float2 v = *(const float2*)(hA + ci * LBUF + (l - off));
#pragma unroll
                    for (int co = 0; co < 8; co++) {
                        float wk = Wc[OCK + (((i - 1) * 3 + w) * 8 + ci) * 8 + co];
                        acc0[co] = fmaf(v.x, wk, acc0[co]); acc1[co] = fmaf(v.y, wk, acc1[co]);
                    }
                }
            }
            float m0 = 0.0f, m1 = 0.0f;
#pragma unroll
            for (int co = 0; co < 8; co++) {
                float mw = Wc[OMIX + i * 8 + co];
                m0 = fmaf(fmaxf(acc0[co], 0.0f), mw, m0);
                m1 = fmaf(fmaxf(acc1[co], 0.0f), mw, m1);
            }
            oacc[l - (LBUF - FRAME)]     += m0;
            oacc[l - (LBUF - FRAME) + 1] += m1;
        }
        __syncthreads();
        if (tid < FRAME) out[b * FRAME + tid] = oacc[tid];
    }
}

static const int SMEM_BYTES = (17 * LBUF + FRAME) * (int)sizeof(float);

extern "C" void kernel_launch(void* const* d_in, const int* in_sizes, int n_in,
                              void* d_out, int out_size) {
    (void)in_sizes; (void)n_in; (void)out_size;
    cudaFuncSetAttribute(wavenet_kernel, cudaFuncAttributeMaxDynamicSharedMemorySize, SMEM_BYTES);

    pack_weights<<<(NW + 511) / 512, 512>>>(
        (const float*)d_in[1], (const float*)d_in[2], (const float*)d_in[3],
        (const float*)d_in[4], (const float*)d_in[5], (const float*)d_in[6],
        (const float*)d_in[7]);

    void* wp = nullptr;
    cudaGetSymbolAddress(&wp, Wstage);
    cudaMemcpyToSymbolAsync(Wc, wp, NW * sizeof(float), 0, cudaMemcpyDeviceToDevice, 0);

    wavenet_kernel<<<128, NTH, SMEM_BYTES>>>((const float*)d_in[0], (float*)d_out);
}